// round 1
// baseline (speedup 1.0000x reference)
#include <cuda_runtime.h>

#define N_SRC1 500000
#define N_DST1 100000
#define E1     1500000
#define N_DST2 20000
#define E2     200000
#define IN_F   128
#define H_F    256
#define N_CLS  47

// ---------------- scratch (device globals: no allocs allowed) ----------------
__device__ float g_hn1[(size_t)N_DST1 * IN_F];   // layer1 neighbor mean (51.2 MB)
__device__ float g_h[(size_t)N_DST1 * H_F];      // layer1 output       (102.4 MB)
__device__ float g_hn2[(size_t)N_DST2 * H_F];    // layer2 neighbor mean (20.5 MB)

__device__ int g_cnt1[N_DST1];
__device__ int g_row1[N_DST1 + 1];
__device__ int g_cur1[N_DST1];
__device__ int g_eidx1[E1];

__device__ int g_cnt2[N_DST2];
__device__ int g_row2[N_DST2 + 1];
__device__ int g_cur2[N_DST2];
__device__ int g_eidx2[E2];

// ---------------- CSR build ----------------
__global__ void k_zero_counts() {
    int i = blockIdx.x * blockDim.x + threadIdx.x;
    if (i < N_DST1) g_cnt1[i] = 0;
    if (i < N_DST2) g_cnt2[i] = 0;
}

__global__ void k_count1(const int* __restrict__ dst) {
    int i = blockIdx.x * blockDim.x + threadIdx.x;
    if (i < E1) atomicAdd(&g_cnt1[dst[i]], 1);
}
__global__ void k_count2(const int* __restrict__ dst) {
    int i = blockIdx.x * blockDim.x + threadIdx.x;
    if (i < E2) atomicAdd(&g_cnt2[dst[i]], 1);
}

// single-block exclusive scan: cnt[n] -> row[n+1], cur[n]=row[n]
template <int NN>
__device__ __forceinline__ void scan_impl(const int* cnt, int* row, int* cur) {
    __shared__ int s[1024];
    int t = threadIdx.x;
    int chunk = (NN + 1023) >> 10;
    int lo = t * chunk;
    int hi = min(lo + chunk, NN);
    int sum = 0;
    for (int i = lo; i < hi; i++) sum += cnt[i];
    s[t] = sum;
    __syncthreads();
    #pragma unroll
    for (int off = 1; off < 1024; off <<= 1) {
        int v = (t >= off) ? s[t - off] : 0;
        __syncthreads();
        if (t >= off) s[t] += v;
        __syncthreads();
    }
    int run = (t == 0) ? 0 : s[t - 1];
    for (int i = lo; i < hi; i++) {
        row[i] = run;
        cur[i] = run;
        run += cnt[i];
    }
    if (t == 0) row[NN] = s[1023];
}

__global__ void k_scan1() { scan_impl<N_DST1>(g_cnt1, g_row1, g_cur1); }
__global__ void k_scan2() { scan_impl<N_DST2>(g_cnt2, g_row2, g_cur2); }

__global__ void k_fill1(const int* __restrict__ src, const int* __restrict__ dst) {
    int i = blockIdx.x * blockDim.x + threadIdx.x;
    if (i < E1) {
        int p = atomicAdd(&g_cur1[dst[i]], 1);
        g_eidx1[p] = src[i];
    }
}
__global__ void k_fill2(const int* __restrict__ src, const int* __restrict__ dst) {
    int i = blockIdx.x * blockDim.x + threadIdx.x;
    if (i < E2) {
        int p = atomicAdd(&g_cur2[dst[i]], 1);
        g_eidx2[p] = src[i];
    }
}

// ---------------- aggregation (warp per dst node) ----------------
__global__ void k_agg1(const float4* __restrict__ x4) {
    int w = (blockIdx.x * blockDim.x + threadIdx.x) >> 5;
    int lane = threadIdx.x & 31;
    if (w >= N_DST1) return;
    int e0 = g_row1[w], e1 = g_row1[w + 1];
    float4 acc = make_float4(0.f, 0.f, 0.f, 0.f);
    int e = e0;
    for (; e + 1 < e1; e += 2) {
        int sa = g_eidx1[e];
        int sb = g_eidx1[e + 1];
        float4 va = __ldg(&x4[(size_t)sa * 32 + lane]);
        float4 vb = __ldg(&x4[(size_t)sb * 32 + lane]);
        acc.x += va.x + vb.x; acc.y += va.y + vb.y;
        acc.z += va.z + vb.z; acc.w += va.w + vb.w;
    }
    if (e < e1) {
        int sa = g_eidx1[e];
        float4 va = __ldg(&x4[(size_t)sa * 32 + lane]);
        acc.x += va.x; acc.y += va.y; acc.z += va.z; acc.w += va.w;
    }
    float inv = 1.0f / fmaxf((float)(e1 - e0), 1.0f);
    acc.x *= inv; acc.y *= inv; acc.z *= inv; acc.w *= inv;
    ((float4*)g_hn1)[(size_t)w * 32 + lane] = acc;
}

__global__ void k_agg2() {
    int w = (blockIdx.x * blockDim.x + threadIdx.x) >> 5;
    int lane = threadIdx.x & 31;
    if (w >= N_DST2) return;
    const float4* h4 = (const float4*)g_h;
    int e0 = g_row2[w], e1 = g_row2[w + 1];
    float4 a0 = make_float4(0.f, 0.f, 0.f, 0.f);
    float4 a1 = make_float4(0.f, 0.f, 0.f, 0.f);
    for (int e = e0; e < e1; e++) {
        int s = g_eidx2[e];
        float4 v0 = __ldg(&h4[(size_t)s * 64 + lane]);
        float4 v1 = __ldg(&h4[(size_t)s * 64 + lane + 32]);
        a0.x += v0.x; a0.y += v0.y; a0.z += v0.z; a0.w += v0.w;
        a1.x += v1.x; a1.y += v1.y; a1.z += v1.z; a1.w += v1.w;
    }
    float inv = 1.0f / fmaxf((float)(e1 - e0), 1.0f);
    a0.x *= inv; a0.y *= inv; a0.z *= inv; a0.w *= inv;
    a1.x *= inv; a1.y *= inv; a1.z *= inv; a1.w *= inv;
    ((float4*)g_hn2)[(size_t)w * 64 + lane] = a0;
    ((float4*)g_hn2)[(size_t)w * 64 + lane + 32] = a1;
}

// ---------------- layer-1 GEMM: h = relu([x | hn1] @ [Ws;Wn] + b) ----------------
// 128x128 tile, BK=16, 256 threads, 8x8 microtile
__global__ __launch_bounds__(256) void k_gemm1(const float* __restrict__ x,
                                               const float* __restrict__ Ws,
                                               const float* __restrict__ Wn,
                                               const float* __restrict__ b1) {
    __shared__ float As[16][128];
    __shared__ float Bs[16][128];
    int t = threadIdx.x;
    int m0 = blockIdx.y * 128;
    int n0 = blockIdx.x * 128;
    int tm = (t >> 4) << 3;
    int tn = (t & 15) << 3;
    float acc[8][8];
    #pragma unroll
    for (int i = 0; i < 8; i++)
        #pragma unroll
        for (int j = 0; j < 8; j++) acc[i][j] = 0.f;

    for (int kk = 0; kk < 2 * IN_F; kk += 16) {
        const float* Abase = (kk < IN_F) ? (x + kk) : (g_hn1 + (kk - IN_F));
        const float* Bbase = (kk < IN_F) ? (Ws + (size_t)kk * H_F) : (Wn + (size_t)(kk - IN_F) * H_F);
        #pragma unroll
        for (int r = 0; r < 2; r++) {
            int l = t + r * 256;
            int row = l >> 2;
            int q = (l & 3) << 2;
            int grow = m0 + row;
            float4 v = make_float4(0.f, 0.f, 0.f, 0.f);
            if (grow < N_DST1) v = *(const float4*)(Abase + (size_t)grow * IN_F + q);
            As[q + 0][row] = v.x;
            As[q + 1][row] = v.y;
            As[q + 2][row] = v.z;
            As[q + 3][row] = v.w;
        }
        #pragma unroll
        for (int r = 0; r < 2; r++) {
            int l = t + r * 256;
            int k = l >> 5;
            int q = (l & 31) << 2;
            *(float4*)&Bs[k][q] = *(const float4*)(Bbase + (size_t)k * H_F + n0 + q);
        }
        __syncthreads();
        #pragma unroll
        for (int k = 0; k < 16; k++) {
            float4 a0 = *(const float4*)&As[k][tm];
            float4 a1 = *(const float4*)&As[k][tm + 4];
            float4 b0 = *(const float4*)&Bs[k][tn];
            float4 b1v = *(const float4*)&Bs[k][tn + 4];
            float a[8] = {a0.x, a0.y, a0.z, a0.w, a1.x, a1.y, a1.z, a1.w};
            float b[8] = {b0.x, b0.y, b0.z, b0.w, b1v.x, b1v.y, b1v.z, b1v.w};
            #pragma unroll
            for (int i = 0; i < 8; i++)
                #pragma unroll
                for (int j = 0; j < 8; j++) acc[i][j] += a[i] * b[j];
        }
        __syncthreads();
    }
    float bias[8];
    #pragma unroll
    for (int j = 0; j < 8; j++) bias[j] = b1[n0 + tn + j];
    #pragma unroll
    for (int i = 0; i < 8; i++) {
        int row = m0 + tm + i;
        if (row < N_DST1) {
            float4 o0, o1;
            o0.x = fmaxf(acc[i][0] + bias[0], 0.f);
            o0.y = fmaxf(acc[i][1] + bias[1], 0.f);
            o0.z = fmaxf(acc[i][2] + bias[2], 0.f);
            o0.w = fmaxf(acc[i][3] + bias[3], 0.f);
            o1.x = fmaxf(acc[i][4] + bias[4], 0.f);
            o1.y = fmaxf(acc[i][5] + bias[5], 0.f);
            o1.z = fmaxf(acc[i][6] + bias[6], 0.f);
            o1.w = fmaxf(acc[i][7] + bias[7], 0.f);
            float* dstp = g_h + (size_t)row * H_F + n0 + tn;
            *(float4*)dstp = o0;
            *(float4*)(dstp + 4) = o1;
        }
    }
}

// ---------------- layer-2 GEMM: out = h[:20000]@Ws2 + hn2@Wn2 + b2 ----------------
__global__ void k_gemm2(const float* __restrict__ Ws2, const float* __restrict__ Wn2,
                        const float* __restrict__ b2, float* __restrict__ out) {
    int w = (blockIdx.x * blockDim.x + threadIdx.x) >> 5;
    int lane = threadIdx.x & 31;
    if (w >= N_DST2) return;
    const float* hrow = g_h + (size_t)w * H_F;
    const float* nrow = g_hn2 + (size_t)w * H_F;
    int c0 = lane;
    int c1 = lane + 32;
    float acc0 = 0.f, acc1 = 0.f;
    for (int kb = 0; kb < H_F; kb += 32) {
        float av = hrow[kb + lane];
        float bv = nrow[kb + lane];
        #pragma unroll
        for (int kkk = 0; kkk < 32; kkk++) {
            float a = __shfl_sync(0xffffffffu, av, kkk);
            float bn = __shfl_sync(0xffffffffu, bv, kkk);
            int k = kb + kkk;
            acc0 += a * __ldg(&Ws2[k * N_CLS + c0]) + bn * __ldg(&Wn2[k * N_CLS + c0]);
            if (c1 < N_CLS)
                acc1 += a * __ldg(&Ws2[k * N_CLS + c1]) + bn * __ldg(&Wn2[k * N_CLS + c1]);
        }
    }
    out[(size_t)w * N_CLS + c0] = acc0 + b2[c0];
    if (c1 < N_CLS) out[(size_t)w * N_CLS + c1] = acc1 + b2[c1];
}

// ---------------- launch ----------------
extern "C" void kernel_launch(void* const* d_in, const int* in_sizes, int n_in,
                              void* d_out, int out_size) {
    const float* x   = (const float*)d_in[0];
    const float* Ws1 = (const float*)d_in[1];
    const float* Wn1 = (const float*)d_in[2];
    const float* b1  = (const float*)d_in[3];
    const float* Ws2 = (const float*)d_in[4];
    const float* Wn2 = (const float*)d_in[5];
    const float* b2  = (const float*)d_in[6];
    const int* src1  = (const int*)d_in[7];
    const int* dst1  = (const int*)d_in[8];
    const int* src2  = (const int*)d_in[9];
    const int* dst2  = (const int*)d_in[10];
    float* out = (float*)d_out;

    k_zero_counts<<<(N_DST1 + 255) / 256, 256>>>();
    k_count1<<<(E1 + 255) / 256, 256>>>(dst1);
    k_count2<<<(E2 + 255) / 256, 256>>>(dst2);
    k_scan1<<<1, 1024>>>();
    k_scan2<<<1, 1024>>>();
    k_fill1<<<(E1 + 255) / 256, 256>>>(src1, dst1);
    k_fill2<<<(E2 + 255) / 256, 256>>>(src2, dst2);

    k_agg1<<<(N_DST1 * 32 + 255) / 256, 256>>>((const float4*)x);

    dim3 g1(H_F / 128, (N_DST1 + 127) / 128);
    k_gemm1<<<g1, 256>>>(x, Ws1, Wn1, b1);

    k_agg2<<<(N_DST2 * 32 + 255) / 256, 256>>>();

    k_gemm2<<<(N_DST2 * 32 + 255) / 256, 256>>>(Ws2, Wn2, b2, out);
}

// round 2
// speedup vs baseline: 1.0002x; 1.0002x over previous
#include <cuda_runtime.h>

#define N_SRC1 500000
#define N_DST1 100000
#define E1     1500000
#define N_DST2 20000
#define E2     200000
#define IN_F   128
#define H_F    256
#define N_CLS  47

// ---------------- scratch (device globals: no allocs allowed) ----------------
__device__ float g_hn1[(size_t)N_DST1 * IN_F];   // layer1 neighbor mean (51.2 MB)
__device__ float g_h[(size_t)N_DST1 * H_F];      // layer1 output       (102.4 MB)
__device__ float g_hn2[(size_t)N_DST2 * H_F];    // layer2 neighbor mean (20.5 MB)

__device__ int g_cnt1[N_DST1];
__device__ int g_row1[N_DST1 + 1];
__device__ int g_cur1[N_DST1];
__device__ int g_eidx1[E1];

__device__ int g_cnt2[N_DST2];
__device__ int g_row2[N_DST2 + 1];
__device__ int g_cur2[N_DST2];
__device__ int g_eidx2[E2];

// ---------------- CSR build ----------------
__global__ void k_zero_counts() {
    int i = blockIdx.x * blockDim.x + threadIdx.x;
    if (i < N_DST1) g_cnt1[i] = 0;
    if (i < N_DST2) g_cnt2[i] = 0;
}

__global__ void k_count1(const int* __restrict__ dst) {
    int i = blockIdx.x * blockDim.x + threadIdx.x;
    if (i < E1) atomicAdd(&g_cnt1[dst[i]], 1);
}
__global__ void k_count2(const int* __restrict__ dst) {
    int i = blockIdx.x * blockDim.x + threadIdx.x;
    if (i < E2) atomicAdd(&g_cnt2[dst[i]], 1);
}

// single-block exclusive scan: cnt[n] -> row[n+1], cur[n]=row[n]
template <int NN>
__device__ __forceinline__ void scan_impl(const int* cnt, int* row, int* cur) {
    __shared__ int s[1024];
    int t = threadIdx.x;
    int chunk = (NN + 1023) >> 10;
    int lo = t * chunk;
    int hi = min(lo + chunk, NN);
    int sum = 0;
    for (int i = lo; i < hi; i++) sum += cnt[i];
    s[t] = sum;
    __syncthreads();
    #pragma unroll
    for (int off = 1; off < 1024; off <<= 1) {
        int v = (t >= off) ? s[t - off] : 0;
        __syncthreads();
        if (t >= off) s[t] += v;
        __syncthreads();
    }
    int run = (t == 0) ? 0 : s[t - 1];
    for (int i = lo; i < hi; i++) {
        row[i] = run;
        cur[i] = run;
        run += cnt[i];
    }
    if (t == 0) row[NN] = s[1023];
}

__global__ void k_scan1() { scan_impl<N_DST1>(g_cnt1, g_row1, g_cur1); }
__global__ void k_scan2() { scan_impl<N_DST2>(g_cnt2, g_row2, g_cur2); }

__global__ void k_fill1(const int* __restrict__ src, const int* __restrict__ dst) {
    int i = blockIdx.x * blockDim.x + threadIdx.x;
    if (i < E1) {
        int p = atomicAdd(&g_cur1[dst[i]], 1);
        g_eidx1[p] = src[i];
    }
}
__global__ void k_fill2(const int* __restrict__ src, const int* __restrict__ dst) {
    int i = blockIdx.x * blockDim.x + threadIdx.x;
    if (i < E2) {
        int p = atomicAdd(&g_cur2[dst[i]], 1);
        g_eidx2[p] = src[i];
    }
}

// ---------------- aggregation (warp per dst node) ----------------
__global__ void k_agg1(const float4* __restrict__ x4) {
    int w = (blockIdx.x * blockDim.x + threadIdx.x) >> 5;
    int lane = threadIdx.x & 31;
    if (w >= N_DST1) return;
    int e0 = g_row1[w], e1 = g_row1[w + 1];
    float4 acc = make_float4(0.f, 0.f, 0.f, 0.f);
    int e = e0;
    for (; e + 1 < e1; e += 2) {
        int sa = g_eidx1[e];
        int sb = g_eidx1[e + 1];
        float4 va = __ldg(&x4[(size_t)sa * 32 + lane]);
        float4 vb = __ldg(&x4[(size_t)sb * 32 + lane]);
        acc.x += va.x + vb.x; acc.y += va.y + vb.y;
        acc.z += va.z + vb.z; acc.w += va.w + vb.w;
    }
    if (e < e1) {
        int sa = g_eidx1[e];
        float4 va = __ldg(&x4[(size_t)sa * 32 + lane]);
        acc.x += va.x; acc.y += va.y; acc.z += va.z; acc.w += va.w;
    }
    float inv = 1.0f / fmaxf((float)(e1 - e0), 1.0f);
    acc.x *= inv; acc.y *= inv; acc.z *= inv; acc.w *= inv;
    ((float4*)g_hn1)[(size_t)w * 32 + lane] = acc;
}

__global__ void k_agg2() {
    int w = (blockIdx.x * blockDim.x + threadIdx.x) >> 5;
    int lane = threadIdx.x & 31;
    if (w >= N_DST2) return;
    const float4* h4 = (const float4*)g_h;
    int e0 = g_row2[w], e1 = g_row2[w + 1];
    float4 a0 = make_float4(0.f, 0.f, 0.f, 0.f);
    float4 a1 = make_float4(0.f, 0.f, 0.f, 0.f);
    for (int e = e0; e < e1; e++) {
        int s = g_eidx2[e];
        float4 v0 = __ldg(&h4[(size_t)s * 64 + lane]);
        float4 v1 = __ldg(&h4[(size_t)s * 64 + lane + 32]);
        a0.x += v0.x; a0.y += v0.y; a0.z += v0.z; a0.w += v0.w;
        a1.x += v1.x; a1.y += v1.y; a1.z += v1.z; a1.w += v1.w;
    }
    float inv = 1.0f / fmaxf((float)(e1 - e0), 1.0f);
    a0.x *= inv; a0.y *= inv; a0.z *= inv; a0.w *= inv;
    a1.x *= inv; a1.y *= inv; a1.z *= inv; a1.w *= inv;
    ((float4*)g_hn2)[(size_t)w * 64 + lane] = a0;
    ((float4*)g_hn2)[(size_t)w * 64 + lane + 32] = a1;
}

// ---------------- layer-1 GEMM: h = relu([x | hn1] @ [Ws;Wn] + b) ----------------
// 128x128 tile, BK=16, 256 threads, 8x8 microtile
__global__ __launch_bounds__(256) void k_gemm1(const float* __restrict__ x,
                                               const float* __restrict__ Ws,
                                               const float* __restrict__ Wn,
                                               const float* __restrict__ b1) {
    __shared__ float As[16][128];
    __shared__ float Bs[16][128];
    int t = threadIdx.x;
    int m0 = blockIdx.y * 128;
    int n0 = blockIdx.x * 128;
    int tm = (t >> 4) << 3;
    int tn = (t & 15) << 3;
    float acc[8][8];
    #pragma unroll
    for (int i = 0; i < 8; i++)
        #pragma unroll
        for (int j = 0; j < 8; j++) acc[i][j] = 0.f;

    for (int kk = 0; kk < 2 * IN_F; kk += 16) {
        const float* Abase = (kk < IN_F) ? (x + kk) : (g_hn1 + (kk - IN_F));
        const float* Bbase = (kk < IN_F) ? (Ws + (size_t)kk * H_F) : (Wn + (size_t)(kk - IN_F) * H_F);
        #pragma unroll
        for (int r = 0; r < 2; r++) {
            int l = t + r * 256;
            int row = l >> 2;
            int q = (l & 3) << 2;
            int grow = m0 + row;
            float4 v = make_float4(0.f, 0.f, 0.f, 0.f);
            if (grow < N_DST1) v = *(const float4*)(Abase + (size_t)grow * IN_F + q);
            As[q + 0][row] = v.x;
            As[q + 1][row] = v.y;
            As[q + 2][row] = v.z;
            As[q + 3][row] = v.w;
        }
        #pragma unroll
        for (int r = 0; r < 2; r++) {
            int l = t + r * 256;
            int k = l >> 5;
            int q = (l & 31) << 2;
            *(float4*)&Bs[k][q] = *(const float4*)(Bbase + (size_t)k * H_F + n0 + q);
        }
        __syncthreads();
        #pragma unroll
        for (int k = 0; k < 16; k++) {
            float4 a0 = *(const float4*)&As[k][tm];
            float4 a1 = *(const float4*)&As[k][tm + 4];
            float4 b0 = *(const float4*)&Bs[k][tn];
            float4 b1v = *(const float4*)&Bs[k][tn + 4];
            float a[8] = {a0.x, a0.y, a0.z, a0.w, a1.x, a1.y, a1.z, a1.w};
            float b[8] = {b0.x, b0.y, b0.z, b0.w, b1v.x, b1v.y, b1v.z, b1v.w};
            #pragma unroll
            for (int i = 0; i < 8; i++)
                #pragma unroll
                for (int j = 0; j < 8; j++) acc[i][j] += a[i] * b[j];
        }
        __syncthreads();
    }
    float bias[8];
    #pragma unroll
    for (int j = 0; j < 8; j++) bias[j] = b1[n0 + tn + j];
    #pragma unroll
    for (int i = 0; i < 8; i++) {
        int row = m0 + tm + i;
        if (row < N_DST1) {
            float4 o0, o1;
            o0.x = fmaxf(acc[i][0] + bias[0], 0.f);
            o0.y = fmaxf(acc[i][1] + bias[1], 0.f);
            o0.z = fmaxf(acc[i][2] + bias[2], 0.f);
            o0.w = fmaxf(acc[i][3] + bias[3], 0.f);
            o1.x = fmaxf(acc[i][4] + bias[4], 0.f);
            o1.y = fmaxf(acc[i][5] + bias[5], 0.f);
            o1.z = fmaxf(acc[i][6] + bias[6], 0.f);
            o1.w = fmaxf(acc[i][7] + bias[7], 0.f);
            float* dstp = g_h + (size_t)row * H_F + n0 + tn;
            *(float4*)dstp = o0;
            *(float4*)(dstp + 4) = o1;
        }
    }
}

// ---------------- layer-2 GEMM: out = h[:20000]@Ws2 + hn2@Wn2 + b2 ----------------
__global__ void k_gemm2(const float* __restrict__ Ws2, const float* __restrict__ Wn2,
                        const float* __restrict__ b2, float* __restrict__ out) {
    int w = (blockIdx.x * blockDim.x + threadIdx.x) >> 5;
    int lane = threadIdx.x & 31;
    if (w >= N_DST2) return;
    const float* hrow = g_h + (size_t)w * H_F;
    const float* nrow = g_hn2 + (size_t)w * H_F;
    int c0 = lane;
    int c1 = lane + 32;
    float acc0 = 0.f, acc1 = 0.f;
    for (int kb = 0; kb < H_F; kb += 32) {
        float av = hrow[kb + lane];
        float bv = nrow[kb + lane];
        #pragma unroll
        for (int kkk = 0; kkk < 32; kkk++) {
            float a = __shfl_sync(0xffffffffu, av, kkk);
            float bn = __shfl_sync(0xffffffffu, bv, kkk);
            int k = kb + kkk;
            acc0 += a * __ldg(&Ws2[k * N_CLS + c0]) + bn * __ldg(&Wn2[k * N_CLS + c0]);
            if (c1 < N_CLS)
                acc1 += a * __ldg(&Ws2[k * N_CLS + c1]) + bn * __ldg(&Wn2[k * N_CLS + c1]);
        }
    }
    out[(size_t)w * N_CLS + c0] = acc0 + b2[c0];
    if (c1 < N_CLS) out[(size_t)w * N_CLS + c1] = acc1 + b2[c1];
}

// ---------------- launch ----------------
extern "C" void kernel_launch(void* const* d_in, const int* in_sizes, int n_in,
                              void* d_out, int out_size) {
    const float* x   = (const float*)d_in[0];
    const float* Ws1 = (const float*)d_in[1];
    const float* Wn1 = (const float*)d_in[2];
    const float* b1  = (const float*)d_in[3];
    const float* Ws2 = (const float*)d_in[4];
    const float* Wn2 = (const float*)d_in[5];
    const float* b2  = (const float*)d_in[6];
    const int* src1  = (const int*)d_in[7];
    const int* dst1  = (const int*)d_in[8];
    const int* src2  = (const int*)d_in[9];
    const int* dst2  = (const int*)d_in[10];
    float* out = (float*)d_out;

    k_zero_counts<<<(N_DST1 + 255) / 256, 256>>>();
    k_count1<<<(E1 + 255) / 256, 256>>>(dst1);
    k_count2<<<(E2 + 255) / 256, 256>>>(dst2);
    k_scan1<<<1, 1024>>>();
    k_scan2<<<1, 1024>>>();
    k_fill1<<<(E1 + 255) / 256, 256>>>(src1, dst1);
    k_fill2<<<(E2 + 255) / 256, 256>>>(src2, dst2);

    k_agg1<<<(N_DST1 * 32 + 255) / 256, 256>>>((const float4*)x);

    dim3 g1(H_F / 128, (N_DST1 + 127) / 128);
    k_gemm1<<<g1, 256>>>(x, Ws1, Wn1, b1);

    k_agg2<<<(N_DST2 * 32 + 255) / 256, 256>>>();

    k_gemm2<<<(N_DST2 * 32 + 255) / 256, 256>>>(Ws2, Wn2, b2, out);
}

// round 3
// speedup vs baseline: 1.3734x; 1.3732x over previous
#include <cuda_runtime.h>

#define N_SRC1 500000
#define N_DST1 100000
#define E1     1500000
#define N_DST2 20000
#define E2     200000
#define IN_F   128
#define H_F    256
#define N_CLS  47

#define NB1 98   // ceil(N_DST1/1024)
#define NB2 20   // ceil(N_DST2/1024)

// ---------------- scratch (device globals: no allocs allowed) ----------------
__device__ float g_hn1[(size_t)N_DST1 * IN_F];
__device__ float g_h[(size_t)N_DST1 * H_F];
__device__ float g_hn2[(size_t)N_DST2 * H_F];

__device__ int g_cnt1[N_DST1];
__device__ int g_row1[N_DST1 + 1];
__device__ int g_cur1[N_DST1];
__device__ int g_eidx1[E1];

__device__ int g_cnt2[N_DST2];
__device__ int g_row2[N_DST2 + 1];
__device__ int g_cur2[N_DST2];
__device__ int g_eidx2[E2];

__device__ int g_bsum1[128];
__device__ int g_bsum2[128];
__device__ int g_boff1[128];
__device__ int g_boff2[128];

// ---------------- CSR build ----------------
__global__ void k_zero_counts() {
    int i = blockIdx.x * blockDim.x + threadIdx.x;
    if (i < N_DST1) g_cnt1[i] = 0;
    if (i < N_DST2) g_cnt2[i] = 0;
}

__global__ void k_count(const int* __restrict__ d1, const int* __restrict__ d2) {
    int i = blockIdx.x * blockDim.x + threadIdx.x;
    if (i < E1) atomicAdd(&g_cnt1[d1[i]], 1);
    if (i < E2) atomicAdd(&g_cnt2[d2[i]], 1);
}

// phase A: per-1024-chunk sums for both arrays (grid = NB1 + NB2)
__global__ void k_scanA() {
    __shared__ int s[1024];
    int b = blockIdx.x;
    const int* cnt; int n; int* bsum; int bb;
    if (b < NB1) { cnt = g_cnt1; n = N_DST1; bsum = g_bsum1; bb = b; }
    else         { cnt = g_cnt2; n = N_DST2; bsum = g_bsum2; bb = b - NB1; }
    int i = bb * 1024 + threadIdx.x;
    int v = (i < n) ? cnt[i] : 0;
    s[threadIdx.x] = v;
    __syncthreads();
    #pragma unroll
    for (int off = 512; off > 0; off >>= 1) {
        if (threadIdx.x < off) s[threadIdx.x] += s[threadIdx.x + off];
        __syncthreads();
    }
    if (threadIdx.x == 0) bsum[bb] = s[0];
}

// phase B: one block (256 thr) exclusive-scans both block-sum arrays in parallel
__global__ void k_scanB() {
    __shared__ int s1[128];
    __shared__ int s2[128];
    int t = threadIdx.x;
    if (t < 128) s1[t] = (t < NB1) ? g_bsum1[t] : 0;
    else         { int u = t - 128; s2[u] = (u < NB2) ? g_bsum2[u] : 0; }
    __syncthreads();
    #pragma unroll
    for (int off = 1; off < 128; off <<= 1) {
        int v;
        if (t < 128) v = (t >= off) ? s1[t - off] : 0;
        else         { int u = t - 128; v = (u >= off) ? s2[u - off] : 0; }
        __syncthreads();
        if (t < 128) s1[t] += v;
        else         s2[t - 128] += v;
        __syncthreads();
    }
    if (t < 128) { if (t < NB1) g_boff1[t] = (t ? s1[t - 1] : 0); }
    else         { int u = t - 128; if (u < NB2) g_boff2[u] = (u ? s2[u - 1] : 0); }
}

// phase C: local exclusive scan per chunk + block offset -> row/cur
__global__ void k_scanC() {
    __shared__ int s[1024];
    int b = blockIdx.x;
    const int* cnt; int n; int* row; int* cur; int boff; int bb; int etot;
    if (b < NB1) { cnt = g_cnt1; n = N_DST1; row = g_row1; cur = g_cur1; bb = b;       boff = g_boff1[bb]; etot = E1; }
    else         { cnt = g_cnt2; n = N_DST2; row = g_row2; cur = g_cur2; bb = b - NB1; boff = g_boff2[bb]; etot = E2; }
    int t = threadIdx.x;
    int i = bb * 1024 + t;
    int v = (i < n) ? cnt[i] : 0;
    s[t] = v;
    __syncthreads();
    #pragma unroll
    for (int off = 1; off < 1024; off <<= 1) {
        int u = (t >= off) ? s[t - off] : 0;
        __syncthreads();
        s[t] += u;
        __syncthreads();
    }
    int excl = boff + s[t] - v;
    if (i < n) { row[i] = excl; cur[i] = excl; }
    if (i == n - 1) row[n] = etot;
}

__global__ void k_fill(const int* __restrict__ s1, const int* __restrict__ d1,
                       const int* __restrict__ s2, const int* __restrict__ d2) {
    int i = blockIdx.x * blockDim.x + threadIdx.x;
    if (i < E1) {
        int p = atomicAdd(&g_cur1[d1[i]], 1);
        g_eidx1[p] = s1[i];
    }
    if (i < E2) {
        int p = atomicAdd(&g_cur2[d2[i]], 1);
        g_eidx2[p] = s2[i];
    }
}

// ---------------- aggregation (warp per dst node) ----------------
__global__ void k_agg1(const float4* __restrict__ x4) {
    int w = (blockIdx.x * blockDim.x + threadIdx.x) >> 5;
    int lane = threadIdx.x & 31;
    if (w >= N_DST1) return;
    int e0 = g_row1[w], e1 = g_row1[w + 1];
    float4 acc = make_float4(0.f, 0.f, 0.f, 0.f);
    int e = e0;
    for (; e + 3 < e1; e += 4) {
        int sa = g_eidx1[e];
        int sb = g_eidx1[e + 1];
        int sc = g_eidx1[e + 2];
        int sd = g_eidx1[e + 3];
        float4 va = __ldg(&x4[(size_t)sa * 32 + lane]);
        float4 vb = __ldg(&x4[(size_t)sb * 32 + lane]);
        float4 vc = __ldg(&x4[(size_t)sc * 32 + lane]);
        float4 vd = __ldg(&x4[(size_t)sd * 32 + lane]);
        acc.x += (va.x + vb.x) + (vc.x + vd.x);
        acc.y += (va.y + vb.y) + (vc.y + vd.y);
        acc.z += (va.z + vb.z) + (vc.z + vd.z);
        acc.w += (va.w + vb.w) + (vc.w + vd.w);
    }
    for (; e < e1; e++) {
        int sa = g_eidx1[e];
        float4 va = __ldg(&x4[(size_t)sa * 32 + lane]);
        acc.x += va.x; acc.y += va.y; acc.z += va.z; acc.w += va.w;
    }
    float inv = 1.0f / fmaxf((float)(e1 - e0), 1.0f);
    acc.x *= inv; acc.y *= inv; acc.z *= inv; acc.w *= inv;
    ((float4*)g_hn1)[(size_t)w * 32 + lane] = acc;
}

__global__ void k_agg2() {
    int w = (blockIdx.x * blockDim.x + threadIdx.x) >> 5;
    int lane = threadIdx.x & 31;
    if (w >= N_DST2) return;
    const float4* h4 = (const float4*)g_h;
    int e0 = g_row2[w], e1 = g_row2[w + 1];
    float4 a0 = make_float4(0.f, 0.f, 0.f, 0.f);
    float4 a1 = make_float4(0.f, 0.f, 0.f, 0.f);
    for (int e = e0; e < e1; e++) {
        int s = g_eidx2[e];
        float4 v0 = __ldg(&h4[(size_t)s * 64 + lane]);
        float4 v1 = __ldg(&h4[(size_t)s * 64 + lane + 32]);
        a0.x += v0.x; a0.y += v0.y; a0.z += v0.z; a0.w += v0.w;
        a1.x += v1.x; a1.y += v1.y; a1.z += v1.z; a1.w += v1.w;
    }
    float inv = 1.0f / fmaxf((float)(e1 - e0), 1.0f);
    a0.x *= inv; a0.y *= inv; a0.z *= inv; a0.w *= inv;
    a1.x *= inv; a1.y *= inv; a1.z *= inv; a1.w *= inv;
    ((float4*)g_hn2)[(size_t)w * 64 + lane] = a0;
    ((float4*)g_hn2)[(size_t)w * 64 + lane + 32] = a1;
}

// ---------------- layer-1 GEMM: h = relu([x | hn1] @ [Ws;Wn] + b) ----------------
// 128x128 tile, BK=16, 256 threads, 8x8 microtile, double-buffered smem.
__global__ __launch_bounds__(256) void k_gemm1(const float* __restrict__ x,
                                               const float* __restrict__ Ws,
                                               const float* __restrict__ Wn,
                                               const float* __restrict__ b1) {
    __shared__ float As[2][16][128];
    __shared__ float Bs[2][16][128];
    int t = threadIdx.x;
    int m0 = blockIdx.y * 128;
    int n0 = blockIdx.x * 128;
    int tm = (t >> 4) << 3;
    int tn = (t & 15) << 3;

    // per-thread load coordinates (fixed across iterations)
    int a_row = t >> 2;               // 0..63 for r=0, +64 for r=1
    int a_q   = (t & 3) << 2;         // k offset 0,4,8,12
    int b_k0  = t >> 5;               // 0..7 for r=0, +8 for r=1
    int b_q   = (t & 31) << 2;        // n offset

    float acc[8][8];
    #pragma unroll
    for (int i = 0; i < 8; i++)
        #pragma unroll
        for (int j = 0; j < 8; j++) acc[i][j] = 0.f;

    float4 rA[2], rB[2];

    auto load_tile = [&](int kk) {
        const float* Abase = (kk < 8) ? (x + kk * 16) : (g_hn1 + (kk - 8) * 16);
        const float* Bbase = (kk < 8) ? (Ws + (size_t)kk * 16 * H_F)
                                      : (Wn + (size_t)(kk - 8) * 16 * H_F);
        #pragma unroll
        for (int r = 0; r < 2; r++) {
            int row = a_row + r * 64;
            int grow = m0 + row;
            rA[r] = make_float4(0.f, 0.f, 0.f, 0.f);
            if (grow < N_DST1) rA[r] = *(const float4*)(Abase + (size_t)grow * IN_F + a_q);
        }
        #pragma unroll
        for (int r = 0; r < 2; r++) {
            int k = b_k0 + r * 8;
            rB[r] = *(const float4*)(Bbase + (size_t)k * H_F + n0 + b_q);
        }
    };
    auto store_tile = [&](int buf) {
        #pragma unroll
        for (int r = 0; r < 2; r++) {
            int row = a_row + r * 64;
            As[buf][a_q + 0][row] = rA[r].x;
            As[buf][a_q + 1][row] = rA[r].y;
            As[buf][a_q + 2][row] = rA[r].z;
            As[buf][a_q + 3][row] = rA[r].w;
        }
        #pragma unroll
        for (int r = 0; r < 2; r++) {
            int k = b_k0 + r * 8;
            *(float4*)&Bs[buf][k][b_q] = rB[r];
        }
    };

    load_tile(0);
    store_tile(0);
    __syncthreads();

    for (int it = 0; it < 16; it++) {
        int cb = it & 1;
        if (it < 15) load_tile(it + 1);
        #pragma unroll
        for (int k = 0; k < 16; k++) {
            float4 a0 = *(const float4*)&As[cb][k][tm];
            float4 a1 = *(const float4*)&As[cb][k][tm + 4];
            float4 b0 = *(const float4*)&Bs[cb][k][tn];
            float4 b1v = *(const float4*)&Bs[cb][k][tn + 4];
            float a[8] = {a0.x, a0.y, a0.z, a0.w, a1.x, a1.y, a1.z, a1.w};
            float b[8] = {b0.x, b0.y, b0.z, b0.w, b1v.x, b1v.y, b1v.z, b1v.w};
            #pragma unroll
            for (int i = 0; i < 8; i++)
                #pragma unroll
                for (int j = 0; j < 8; j++) acc[i][j] += a[i] * b[j];
        }
        if (it < 15) store_tile(cb ^ 1);
        __syncthreads();
    }

    float bias[8];
    #pragma unroll
    for (int j = 0; j < 8; j++) bias[j] = b1[n0 + tn + j];
    #pragma unroll
    for (int i = 0; i < 8; i++) {
        int row = m0 + tm + i;
        if (row < N_DST1) {
            float4 o0, o1;
            o0.x = fmaxf(acc[i][0] + bias[0], 0.f);
            o0.y = fmaxf(acc[i][1] + bias[1], 0.f);
            o0.z = fmaxf(acc[i][2] + bias[2], 0.f);
            o0.w = fmaxf(acc[i][3] + bias[3], 0.f);
            o1.x = fmaxf(acc[i][4] + bias[4], 0.f);
            o1.y = fmaxf(acc[i][5] + bias[5], 0.f);
            o1.z = fmaxf(acc[i][6] + bias[6], 0.f);
            o1.w = fmaxf(acc[i][7] + bias[7], 0.f);
            float* dstp = g_h + (size_t)row * H_F + n0 + tn;
            *(float4*)dstp = o0;
            *(float4*)(dstp + 4) = o1;
        }
    }
}

// ---------------- layer-2 GEMM (tiled): out = [h|hn2] @ [Ws2;Wn2] + b2 ----------------
// M=20000, N=47, K=512. Tile 128 rows x 48 cols, K-tile 32, 256 threads, 4x6 microtile.
__global__ __launch_bounds__(256) void k_gemm2(const float* __restrict__ Ws2,
                                               const float* __restrict__ Wn2,
                                               const float* __restrict__ b2,
                                               float* __restrict__ out) {
    __shared__ float As[32][128];
    __shared__ float Bs[32][48];
    int t = threadIdx.x;
    int m0 = blockIdx.x * 128;
    int r0 = (t >> 3) * 4;    // 0..124
    int c0 = (t & 7) * 6;     // 0..42

    float acc[4][6];
    #pragma unroll
    for (int i = 0; i < 4; i++)
        #pragma unroll
        for (int j = 0; j < 6; j++) acc[i][j] = 0.f;

    for (int kt = 0; kt < 16; kt++) {
        const float* Ab = (kt < 8) ? g_h : g_hn2;
        const float* Bb = (kt < 8) ? Ws2 : Wn2;
        int koff = (kt < 8) ? kt * 32 : (kt - 8) * 32;

        // A-tile: 128 rows x 32 k
        {
            int row = t >> 1;
            int grow = m0 + row;
            #pragma unroll
            for (int j = 0; j < 4; j++) {
                int kq = (t & 1) * 16 + j * 4;
                float4 v = make_float4(0.f, 0.f, 0.f, 0.f);
                if (grow < N_DST2) v = *(const float4*)(Ab + (size_t)grow * H_F + koff + kq);
                As[kq + 0][row] = v.x;
                As[kq + 1][row] = v.y;
                As[kq + 2][row] = v.z;
                As[kq + 3][row] = v.w;
            }
        }
        // B-tile: 32 k x 47 cols
        for (int l = t; l < 32 * N_CLS; l += 256) {
            int k = l / N_CLS;
            int c = l - k * N_CLS;
            Bs[k][c] = Bb[(size_t)(koff + k) * N_CLS + c];
        }
        __syncthreads();
        #pragma unroll
        for (int k = 0; k < 32; k++) {
            float4 a = *(const float4*)&As[k][r0];
            float av[4] = {a.x, a.y, a.z, a.w};
            float bv[6];
            #pragma unroll
            for (int j = 0; j < 6; j++) bv[j] = Bs[k][c0 + j];
            #pragma unroll
            for (int i = 0; i < 4; i++)
                #pragma unroll
                for (int j = 0; j < 6; j++) acc[i][j] += av[i] * bv[j];
        }
        __syncthreads();
    }

    #pragma unroll
    for (int i = 0; i < 4; i++) {
        int row = m0 + r0 + i;
        if (row < N_DST2) {
            #pragma unroll
            for (int j = 0; j < 6; j++) {
                int c = c0 + j;
                if (c < N_CLS) out[(size_t)row * N_CLS + c] = acc[i][j] + b2[c];
            }
        }
    }
}

// ---------------- launch ----------------
extern "C" void kernel_launch(void* const* d_in, const int* in_sizes, int n_in,
                              void* d_out, int out_size) {
    const float* x   = (const float*)d_in[0];
    const float* Ws1 = (const float*)d_in[1];
    const float* Wn1 = (const float*)d_in[2];
    const float* b1  = (const float*)d_in[3];
    const float* Ws2 = (const float*)d_in[4];
    const float* Wn2 = (const float*)d_in[5];
    const float* b2  = (const float*)d_in[6];
    const int* src1  = (const int*)d_in[7];
    const int* dst1  = (const int*)d_in[8];
    const int* src2  = (const int*)d_in[9];
    const int* dst2  = (const int*)d_in[10];
    float* out = (float*)d_out;

    k_zero_counts<<<(N_DST1 + 255) / 256, 256>>>();
    k_count<<<(E1 + 255) / 256, 256>>>(dst1, dst2);
    k_scanA<<<NB1 + NB2, 1024>>>();
    k_scanB<<<1, 256>>>();
    k_scanC<<<NB1 + NB2, 1024>>>();
    k_fill<<<(E1 + 255) / 256, 256>>>(src1, dst1, src2, dst2);

    k_agg1<<<(N_DST1 * 32 + 255) / 256, 256>>>((const float4*)x);

    dim3 g1(H_F / 128, (N_DST1 + 127) / 128);
    k_gemm1<<<g1, 256>>>(x, Ws1, Wn1, b1);

    k_agg2<<<(N_DST2 * 32 + 255) / 256, 256>>>();

    k_gemm2<<<(N_DST2 + 127) / 128, 256>>>(Ws2, Wn2, b2, out);
}